// round 1
// baseline (speedup 1.0000x reference)
#include <cuda_runtime.h>

// ---------------------------------------------------------------------------
// StyleBlock: upsample(2x bilinear) -> modconv3x3(512->256,demod)+lrelu
//             -> modconv3x3(256->256,demod)+lrelu (=h)
//             -> modconv1x1(256->3,no demod)+lrelu (=rgb)
// Shapes: x[4,512,64,64], w[4,512]; out = h[4,256,128,128] ++ rgb[4,3,128,128]
//
// Modulated conv rewrite: scale input channels by style, shared-weight conv,
// scale output by demod factor d[b,co] = rsqrt(sum_ci s^2 * wsq + eps).
// ---------------------------------------------------------------------------

#define B_       4
#define CIN1     512
#define COUT     256
#define HW       128
#define WD       512
#define LRELU_S  0.2f

// scratch (device globals: no allocation allowed)
__device__ float g_xum[B_ * CIN1 * HW * HW];   // upsampled * s1   (134 MB)
__device__ float g_h1m[B_ * COUT * HW * HW];   // lrelu(conv1) * s2 (67 MB)
__device__ float g_s1[B_ * CIN1];
__device__ float g_s2[B_ * COUT];
__device__ float g_s3[B_ * COUT];
__device__ float g_d1[B_ * COUT];
__device__ float g_d2[B_ * COUT];
__device__ float g_wsq1[COUT * CIN1];
__device__ float g_wsq2[COUT * COUT];

// s[b,c] = w[b,:] . aw[c,:] + ab[c]
__global__ void style_kernel(const float* __restrict__ w, const float* __restrict__ aw,
                             const float* __restrict__ ab, float* __restrict__ s, int C) {
    int i = blockIdx.x * blockDim.x + threadIdx.x;
    if (i >= B_ * C) return;
    int b = i / C, c = i - b * C;
    const float* wr = w + b * WD;
    const float* ar = aw + (size_t)c * WD;
    float acc = 0.f;
#pragma unroll 8
    for (int k = 0; k < WD; k++) acc += wr[k] * ar[k];
    s[i] = acc + ab[c];
}

// wsq[co,ci] = sum_k w[co,ci,k]^2   (3x3 kernels)
__global__ void wsq_kernel(const float* __restrict__ w, float* __restrict__ wsq, int n) {
    int i = blockIdx.x * blockDim.x + threadIdx.x;
    if (i >= n) return;
    float a = 0.f;
#pragma unroll
    for (int k = 0; k < 9; k++) { float v = w[(size_t)i * 9 + k]; a += v * v; }
    wsq[i] = a;
}

// d[b,co] = 1/sqrt( sum_ci s[b,ci]^2 * wsq[co,ci] + 1e-8 )
__global__ void demod_kernel(const float* __restrict__ s, const float* __restrict__ wsq,
                             float* __restrict__ d, int Cin) {
    int i = blockIdx.x * blockDim.x + threadIdx.x;
    if (i >= B_ * COUT) return;
    int b = i >> 8, co = i & 255;
    const float* sr = s + b * Cin;
    const float* wr = wsq + (size_t)co * Cin;
    float acc = 0.f;
    for (int c = 0; c < Cin; c++) { float sv = sr[c]; acc += sv * sv * wr[c]; }
    d[i] = 1.0f / sqrtf(acc + 1e-8f);
}

// half-pixel bilinear 64->128 upsample, times style s1[b,ci]
__global__ void upmod_kernel(const float* __restrict__ x, const float* __restrict__ s1,
                             float* __restrict__ out) {
    int idx = blockIdx.x * blockDim.x + threadIdx.x;
    if (idx >= B_ * CIN1 * HW * HW) return;
    int xo = idx & 127;
    int yo = (idx >> 7) & 127;
    int bc = idx >> 14;                 // b*512 + ci
    float sx = xo * 0.5f - 0.25f;
    float sy = yo * 0.5f - 0.25f;
    int x0 = (int)floorf(sx), y0 = (int)floorf(sy);
    float fx = sx - (float)x0, fy = sy - (float)y0;
    int x0c = max(x0, 0), x1c = min(x0 + 1, 63);
    int y0c = max(y0, 0), y1c = min(y0 + 1, 63);
    const float* p = x + (size_t)bc * 64 * 64;
    float v00 = p[y0c * 64 + x0c], v01 = p[y0c * 64 + x1c];
    float v10 = p[y1c * 64 + x0c], v11 = p[y1c * 64 + x1c];
    float v = (1.f - fy) * ((1.f - fx) * v00 + fx * v01)
            + fy        * ((1.f - fx) * v10 + fx * v11);
    out[idx] = v * s1[bc];
}

// Direct 3x3 conv, pad 1, Cout=256, batch 4.
// Block: 16x16 spatial tile, 16 output channels. 256 threads:
//   group = tid/64 (4 co each), 64 threads = 8x8, each thread 2x2 pixels.
// Epilogue: *demod + bias, leaky relu, optional *postscale (style of next conv).
template <int CIN>
__global__ void __launch_bounds__(256)
conv3x3_kernel(const float* __restrict__ in, const float* __restrict__ wgt,
               const float* __restrict__ bias, const float* __restrict__ demod,
               const float* __restrict__ postscale, float* __restrict__ out) {
    constexpr int CS = 4;               // ci per iteration
    __shared__ float s_in[CS][18][20];
    __shared__ float s_w[CS][16][10];

    const int tid = threadIdx.x;
    const int tileX = blockIdx.x, tileY = blockIdx.y;
    const int b  = blockIdx.z >> 4;
    const int cb = blockIdx.z & 15;
    const int group = tid >> 6;         // 0..3
    const int lid = tid & 63;
    const int px = (lid & 7) * 2;
    const int py = (lid >> 3) * 2;
    const int gx0 = tileX * 16 - 1, gy0 = tileY * 16 - 1;

    float acc[4][2][2];
#pragma unroll
    for (int q = 0; q < 4; q++)
#pragma unroll
        for (int oy = 0; oy < 2; oy++)
#pragma unroll
            for (int ox = 0; ox < 2; ox++) acc[q][oy][ox] = 0.f;

    for (int ci0 = 0; ci0 < CIN; ci0 += CS) {
        __syncthreads();
        // input patch: CS x 18 x 18, zero-padded outside [0,128)
        for (int i = tid; i < CS * 18 * 18; i += 256) {
            int cs = i / 324; int rem = i - cs * 324;
            int ry = rem / 18, rx = rem - ry * 18;
            int gy = gy0 + ry, gx = gx0 + rx;
            float v = 0.f;
            if ((unsigned)gy < (unsigned)HW && (unsigned)gx < (unsigned)HW)
                v = in[(((size_t)b * CIN + ci0 + cs) * HW + gy) * HW + gx];
            s_in[cs][ry][rx] = v;
        }
        // weights: CS x 16co x 9
        for (int i = tid; i < CS * 16 * 9; i += 256) {
            int cs = i / 144; int rem = i - cs * 144;
            int cq = rem / 9, k = rem - cq * 9;
            s_w[cs][cq][k] = wgt[(((size_t)(cb * 16 + cq)) * CIN + ci0 + cs) * 9 + k];
        }
        __syncthreads();
#pragma unroll
        for (int cs = 0; cs < CS; cs++) {
            float p[4][4];
#pragma unroll
            for (int dy = 0; dy < 4; dy++)
#pragma unroll
                for (int dx = 0; dx < 4; dx++) p[dy][dx] = s_in[cs][py + dy][px + dx];
#pragma unroll
            for (int cq = 0; cq < 4; cq++) {
                float wv[9];
#pragma unroll
                for (int k = 0; k < 9; k++) wv[k] = s_w[cs][group * 4 + cq][k];
#pragma unroll
                for (int oy = 0; oy < 2; oy++)
#pragma unroll
                    for (int ox = 0; ox < 2; ox++) {
                        float a = acc[cq][oy][ox];
#pragma unroll
                        for (int ky = 0; ky < 3; ky++)
#pragma unroll
                            for (int kx = 0; kx < 3; kx++)
                                a += wv[ky * 3 + kx] * p[oy + ky][ox + kx];
                        acc[cq][oy][ox] = a;
                    }
            }
        }
    }

#pragma unroll
    for (int cq = 0; cq < 4; cq++) {
        int co = cb * 16 + group * 4 + cq;
        float dm = demod[b * COUT + co];
        float bi = bias[co];
        float ps = postscale ? postscale[b * COUT + co] : 1.0f;
#pragma unroll
        for (int oy = 0; oy < 2; oy++)
#pragma unroll
            for (int ox = 0; ox < 2; ox++) {
                float v = acc[cq][oy][ox] * dm + bi;
                v = v > 0.f ? v : LRELU_S * v;
                v *= ps;
                out[(((size_t)b * COUT + co) * HW + tileY * 16 + py + oy) * HW
                    + tileX * 16 + px + ox] = v;
            }
    }
}

// 1x1 conv 256->3 (modulated by s3, no demod) + bias + lrelu
__global__ void rgb_kernel(const float* __restrict__ h, const float* __restrict__ w3,
                           const float* __restrict__ b3, const float* __restrict__ s3,
                           float* __restrict__ rgb) {
    int idx = blockIdx.x * blockDim.x + threadIdx.x;
    if (idx >= B_ * HW * HW) return;
    int b = idx >> 14;
    int pix = idx & 16383;
    float a0 = 0.f, a1 = 0.f, a2 = 0.f;
    const float* hb = h + (size_t)b * COUT * HW * HW + pix;
    const float* s = s3 + b * COUT;
    for (int c = 0; c < COUT; c++) {
        float hv = hb[(size_t)c * HW * HW] * s[c];
        a0 += w3[c] * hv;
        a1 += w3[COUT + c] * hv;
        a2 += w3[2 * COUT + c] * hv;
    }
    float r0 = a0 + b3[0]; r0 = r0 > 0.f ? r0 : LRELU_S * r0;
    float r1 = a1 + b3[1]; r1 = r1 > 0.f ? r1 : LRELU_S * r1;
    float r2 = a2 + b3[2]; r2 = r2 > 0.f ? r2 : LRELU_S * r2;
    rgb[((size_t)b * 3 + 0) * HW * HW + pix] = r0;
    rgb[((size_t)b * 3 + 1) * HW * HW + pix] = r1;
    rgb[((size_t)b * 3 + 2) * HW * HW + pix] = r2;
}

extern "C" void kernel_launch(void* const* d_in, const int* in_sizes, int n_in,
                              void* d_out, int out_size) {
    const float* x   = (const float*)d_in[0];
    const float* w   = (const float*)d_in[1];
    const float* w1  = (const float*)d_in[2];
    const float* b1  = (const float*)d_in[3];
    const float* a1w = (const float*)d_in[4];
    const float* a1b = (const float*)d_in[5];
    const float* w2  = (const float*)d_in[6];
    const float* b2  = (const float*)d_in[7];
    const float* a2w = (const float*)d_in[8];
    const float* a2b = (const float*)d_in[9];
    const float* w3  = (const float*)d_in[10];
    const float* b3  = (const float*)d_in[11];
    const float* a3w = (const float*)d_in[12];
    const float* a3b = (const float*)d_in[13];

    float* out_h   = (float*)d_out;                               // [4,256,128,128]
    float* out_rgb = out_h + (size_t)B_ * COUT * HW * HW;         // [4,3,128,128]

    float *xum, *h1m, *s1, *s2, *s3, *d1, *d2, *wsq1, *wsq2;
    cudaGetSymbolAddress((void**)&xum,  g_xum);
    cudaGetSymbolAddress((void**)&h1m,  g_h1m);
    cudaGetSymbolAddress((void**)&s1,   g_s1);
    cudaGetSymbolAddress((void**)&s2,   g_s2);
    cudaGetSymbolAddress((void**)&s3,   g_s3);
    cudaGetSymbolAddress((void**)&d1,   g_d1);
    cudaGetSymbolAddress((void**)&d2,   g_d2);
    cudaGetSymbolAddress((void**)&wsq1, g_wsq1);
    cudaGetSymbolAddress((void**)&wsq2, g_wsq2);

    // weight-square sums
    wsq_kernel<<<(COUT * CIN1 + 255) / 256, 256>>>(w1, wsq1, COUT * CIN1);
    wsq_kernel<<<(COUT * COUT + 255) / 256, 256>>>(w2, wsq2, COUT * COUT);

    // styles
    style_kernel<<<(B_ * CIN1 + 255) / 256, 256>>>(w, a1w, a1b, s1, CIN1);
    style_kernel<<<(B_ * COUT + 255) / 256, 256>>>(w, a2w, a2b, s2, COUT);
    style_kernel<<<(B_ * COUT + 255) / 256, 256>>>(w, a3w, a3b, s3, COUT);

    // demod factors
    demod_kernel<<<(B_ * COUT + 255) / 256, 256>>>(s1, wsq1, d1, CIN1);
    demod_kernel<<<(B_ * COUT + 255) / 256, 256>>>(s2, wsq2, d2, COUT);

    // upsample + modulate by s1
    int n_up = B_ * CIN1 * HW * HW;
    upmod_kernel<<<n_up / 256, 256>>>(x, s1, xum);

    // conv1: 512 -> 256, epilogue: *d1 + b1, lrelu, *s2 (pre-modulates conv2 input)
    {
        dim3 grid(HW / 16, HW / 16, B_ * (COUT / 16));
        conv3x3_kernel<CIN1><<<grid, 256>>>(xum, w1, b1, d1, s2, h1m);
    }
    // conv2: 256 -> 256, epilogue: *d2 + b2, lrelu -> h (output)
    {
        dim3 grid(HW / 16, HW / 16, B_ * (COUT / 16));
        conv3x3_kernel<COUT><<<grid, 256>>>(h1m, w2, b2, d2, (const float*)nullptr, out_h);
    }
    // to_rgb: 1x1, modulate input by s3, no demod
    rgb_kernel<<<(B_ * HW * HW + 255) / 256, 256>>>(out_h, w3, b3, s3, out_rgb);
}

// round 5
// speedup vs baseline: 4.7499x; 4.7499x over previous
#include <cuda_runtime.h>
#include <cstdint>

#define B_       4
#define COUT     256
#define HW       128
#define WD       512
#define LRELU_S  0.2f

// ---------------- device scratch (zero-initialized; borders stay zero) ----
__device__ float g_xum[B_ * 130 * 130 * 512];   // padded NHWC, tf32, premod s1
__device__ float g_h1m[B_ * 130 * 130 * 256];   // padded NHWC, tf32, premod s2
__device__ float g_h2 [B_ * 128 * 128 * 256];   // NHWC, fp32 (h before layout swap)
__device__ float g_wpk1[9 * 256 * 512];         // [tap][co][ci] tf32
__device__ float g_wpk2[9 * 256 * 256];
__device__ float g_wm3[B_ * 3 * 256];           // rgb weights premod s3
__device__ float g_s1[B_ * 512];
__device__ float g_s2[B_ * 256];
__device__ float g_s3[B_ * 256];
__device__ float g_d1[B_ * 256];
__device__ float g_d2[B_ * 256];
__device__ float g_wsq1[256 * 512];
__device__ float g_wsq2[256 * 256];

// ---------------- helpers -------------------------------------------------
__device__ __forceinline__ uint32_t smem_u32(const void* p) {
    uint32_t a;
    asm("{ .reg .u64 t; cvta.to.shared.u64 t, %1; cvt.u32.u64 %0, t; }" : "=r"(a) : "l"(p));
    return a;
}
__device__ __forceinline__ float to_tf32(float x) {
    float r; asm("cvt.rna.tf32.f32 %0, %1;" : "=f"(r) : "f"(x)); return r;
}
__device__ __forceinline__ void cp16(uint32_t dst, const void* src) {
    asm volatile("cp.async.ca.shared.global [%0], [%1], 16;" :: "r"(dst), "l"(src));
}
__device__ __forceinline__ void mma_tf32(float* c, const uint32_t* a, const uint32_t* b) {
    asm volatile(
        "mma.sync.aligned.m16n8k8.row.col.f32.tf32.tf32.f32 "
        "{%0,%1,%2,%3}, {%4,%5,%6,%7}, {%8,%9}, {%0,%1,%2,%3};"
        : "+f"(c[0]), "+f"(c[1]), "+f"(c[2]), "+f"(c[3])
        : "r"(a[0]), "r"(a[1]), "r"(a[2]), "r"(a[3]), "r"(b[0]), "r"(b[1]));
}

// ---------------- small kernels ------------------------------------------
__global__ void style_warp(const float* __restrict__ w, const float* __restrict__ aw,
                           const float* __restrict__ ab, float* __restrict__ s, int C) {
    int g = (blockIdx.x * blockDim.x + threadIdx.x) >> 5;
    int lane = threadIdx.x & 31;
    if (g >= B_ * C) return;
    int b = g / C, c = g - b * C;
    const float* wr = w + b * WD;
    const float* ar = aw + (size_t)c * WD;
    float acc = 0.f;
#pragma unroll
    for (int k = 0; k < WD / 32; k++) acc += wr[lane + 32 * k] * ar[lane + 32 * k];
#pragma unroll
    for (int o = 16; o; o >>= 1) acc += __shfl_xor_sync(~0u, acc, o);
    if (!lane) s[g] = acc + ab[c];
}

__global__ void wsq_kernel(const float* __restrict__ w, float* __restrict__ wsq, int n) {
    int i = blockIdx.x * blockDim.x + threadIdx.x;
    if (i >= n) return;
    float a = 0.f;
#pragma unroll
    for (int k = 0; k < 9; k++) { float v = w[(size_t)i * 9 + k]; a += v * v; }
    wsq[i] = a;
}

__global__ void demod_warp(const float* __restrict__ s, const float* __restrict__ wsq,
                           float* __restrict__ d, int Cin) {
    int g = (blockIdx.x * blockDim.x + threadIdx.x) >> 5;
    int lane = threadIdx.x & 31;
    if (g >= B_ * 256) return;
    int b = g >> 8, co = g & 255;
    const float* sr = s + b * Cin;
    const float* wr = wsq + (size_t)co * Cin;
    float acc = 0.f;
    for (int c = lane; c < Cin; c += 32) { float sv = sr[c]; acc += sv * sv * wr[c]; }
#pragma unroll
    for (int o = 16; o; o >>= 1) acc += __shfl_xor_sync(~0u, acc, o);
    if (!lane) d[g] = rsqrtf(acc + 1e-8f);
}

__global__ void prepack_kernel(const float* __restrict__ w, float* __restrict__ wpk, int CIN) {
    int idx = blockIdx.x * 256 + threadIdx.x;
    if (idx >= 9 * 256 * CIN) return;
    int ci = idx % CIN; int t = idx / CIN; int co = t & 255; int tap = t >> 8;
    wpk[idx] = to_tf32(w[((size_t)co * CIN + ci) * 9 + tap]);
}

__global__ void rgbw_kernel(const float* __restrict__ w3, const float* __restrict__ s3,
                            float* __restrict__ wm3) {
    int i = blockIdx.x * 256 + threadIdx.x;
    if (i >= B_ * 3 * 256) return;
    int c = i & 255; int t = i >> 8; int r = t % 3; int b = t / 3;
    wm3[i] = w3[r * 256 + c] * s3[b * 256 + c];
}

// bilinear 2x upsample (half-pixel, edge clamp) * s1 -> padded NHWC tf32
__global__ void __launch_bounds__(256)
upmod_kernel(const float* __restrict__ x, const float* __restrict__ s1,
             float* __restrict__ out) {
    __shared__ float st[2][32][21];
    const int tid = threadIdx.x;
    const int x0 = blockIdx.x * 32;
    const int y  = blockIdx.y;
    const int b  = blockIdx.z >> 4;
    const int ci0 = (blockIdx.z & 15) * 32;
    const int y0i = (y - 1) >> 1;
    const int yrow[2] = { max(y0i, 0), min(y0i + 1, 63) };
    const float fy = (y & 1) ? 0.25f : 0.75f;
    const int xs0 = (x0 >> 1) - 1;
    for (int t = tid; t < 32 * 2 * 18; t += 256) {
        int xi = t % 18;
        int rr = (t / 18) & 1;
        int ci = t / 36;
        int xs = min(max(xs0 + xi, 0), 63);
        st[rr][ci][xi] = x[(((size_t)b * 512 + ci0 + ci) * 64 + yrow[rr]) * 64 + xs];
    }
    __syncthreads();
    const int ci = tid & 31;
    const int jg = tid >> 5;
    const float sv = s1[b * 512 + ci0 + ci];
    float* ob = out + (((size_t)b * 130 + 1 + y) * 130 + 1 + x0) * 512 + ci0 + ci;
#pragma unroll
    for (int q = 0; q < 4; q++) {
        int j = jg * 4 + q;
        int xi = (j + 1) >> 1;
        float fx = (j & 1) ? 0.25f : 0.75f;
        float v0 = st[0][ci][xi] * (1.f - fx) + st[0][ci][xi + 1] * fx;
        float v1 = st[1][ci][xi] * (1.f - fx) + st[1][ci][xi + 1] * fx;
        ob[(size_t)j * 512] = to_tf32((v0 * (1.f - fy) + v1 * fy) * sv);
    }
}

// ---------------- tf32 mma.sync implicit-GEMM 3x3 conv --------------------
// CTA: M = 256 pixels (2 rows of 128, blockIdx.x), N = 128 co (blockIdx.y), b = z.
// 8 warps = 4(M) x 2(N), warp tile 64x64 via m16n8k8.
// smem: act [2][256][36], wgt [2][128][36] (stride 36 -> conflict-free frags).
template<int CIN, int PADOUT, bool HAS_PS>
__global__ void __launch_bounds__(256, 1)
conv3x3_mma(const float* __restrict__ in, const float* __restrict__ wpk,
            const float* __restrict__ bias, const float* __restrict__ demod,
            const float* __restrict__ postscale, float* __restrict__ out) {
    constexpr int CPT = CIN / 32;
    constexpr int NCH = 9 * CPT;
    constexpr int PADIN = 130;
    constexpr int ACT_F = 256 * 36;     // floats per act stage
    constexpr int W_F   = 128 * 36;
    extern __shared__ float smf[];
    const uint32_t smb = smem_u32(smf);

    const int tid = threadIdx.x;
    const int wid = tid >> 5, lane = tid & 31;
    const int gq = lane >> 2, tg = lane & 3;
    const int wm = wid >> 1;            // 0..3 (pixel quarter)
    const int wn = wid & 1;             // 0..1 (co half)
    const int y0 = blockIdx.x * 2;
    const int co0 = blockIdx.y * 128;
    const int b  = blockIdx.z;

    float acc[4][8][4];
#pragma unroll
    for (int mi = 0; mi < 4; mi++)
#pragma unroll
        for (int ni = 0; ni < 8; ni++)
#pragma unroll
            for (int k = 0; k < 4; k++) acc[mi][ni][k] = 0.f;

    auto issue = [&](int i, int s) {
        const int tap = i / CPT;
        const int cc = (i - tap * CPT) * 32;
        const int dy = tap / 3 - 1, dx = tap % 3 - 1;
        const float* abase = in + ((((size_t)b * PADIN + (y0 + dy + 1)) * PADIN + (1 + dx)) * CIN + cc);
        const uint32_t adst = smb + s * (ACT_F * 4);
#pragma unroll
        for (int r = 0; r < 8; r++) {
            int t = tid + r * 256;
            int row = t >> 3, j = t & 7;
            const float* src = abase + (size_t)(row >> 7) * (PADIN * CIN) + (size_t)(row & 127) * CIN + j * 4;
            cp16(adst + (uint32_t)(row * 36 + j * 4) * 4, src);
        }
        const float* wbase = wpk + ((size_t)(tap * 256 + co0)) * CIN + cc;
        const uint32_t wdst = smb + (2 * ACT_F + s * W_F) * 4;
#pragma unroll
        for (int r = 0; r < 4; r++) {
            int t = tid + r * 256;
            int row = t >> 3, j = t & 7;
            cp16(wdst + (uint32_t)(row * 36 + j * 4) * 4, wbase + (size_t)row * CIN + j * 4);
        }
        asm volatile("cp.async.commit_group;" ::: "memory");
    };

    issue(0, 0);
    for (int i = 0; i < NCH; i++) {
        const int s = i & 1;
        if (i + 1 < NCH) {
            issue(i + 1, s ^ 1);
            asm volatile("cp.async.wait_group 1;" ::: "memory");
        } else {
            asm volatile("cp.async.wait_group 0;" ::: "memory");
        }
        __syncthreads();

        const float* As_ = smf + s * ACT_F;
        const float* Ws_ = smf + 2 * ACT_F + s * W_F;
#pragma unroll
        for (int k8 = 0; k8 < 4; k8++) {
            const int k0 = k8 * 8;
            uint32_t af[4][4];
#pragma unroll
            for (int mi = 0; mi < 4; mi++) {
                const float* ap = As_ + (wm * 64 + mi * 16) * 36 + k0;
                af[mi][0] = __float_as_uint(ap[gq * 36 + tg]);
                af[mi][1] = __float_as_uint(ap[(gq + 8) * 36 + tg]);
                af[mi][2] = __float_as_uint(ap[gq * 36 + tg + 4]);
                af[mi][3] = __float_as_uint(ap[(gq + 8) * 36 + tg + 4]);
            }
#pragma unroll
            for (int ni = 0; ni < 8; ni++) {
                const float* bp = Ws_ + (wn * 64 + ni * 8 + gq) * 36 + k0;
                uint32_t bf[2];
                bf[0] = __float_as_uint(bp[tg]);
                bf[1] = __float_as_uint(bp[tg + 4]);
#pragma unroll
                for (int mi = 0; mi < 4; mi++) mma_tf32(acc[mi][ni], af[mi], bf);
            }
        }
        __syncthreads();
    }

    // epilogue -> NHWC (PADOUT=130 shifts by +1 border, 128 = unpadded)
    constexpr int OFS = (PADOUT == 130) ? 1 : 0;
#pragma unroll
    for (int ni = 0; ni < 8; ni++) {
        const int co = co0 + wn * 64 + ni * 8 + 2 * tg;
        const float dm0 = demod[b * 256 + co],  dm1 = demod[b * 256 + co + 1];
        const float bi0 = bias[co],             bi1 = bias[co + 1];
        float ps0 = 1.f, ps1 = 1.f;
        if (HAS_PS) { ps0 = postscale[b * 256 + co]; ps1 = postscale[b * 256 + co + 1]; }
#pragma unroll
        for (int mi = 0; mi < 4; mi++) {
#pragma unroll
            for (int h = 0; h < 2; h++) {
                const int m = wm * 64 + mi * 16 + gq + h * 8;
                const int y = y0 + (m >> 7), xx = m & 127;
                float v0 = acc[mi][ni][2 * h + 0] * dm0 + bi0;
                float v1 = acc[mi][ni][2 * h + 1] * dm1 + bi1;
                v0 = v0 > 0.f ? v0 : LRELU_S * v0;
                v1 = v1 > 0.f ? v1 : LRELU_S * v1;
                float2 o;
                if (HAS_PS) { o.x = to_tf32(v0 * ps0); o.y = to_tf32(v1 * ps1); }
                else        { o.x = v0;                o.y = v1; }
                *(float2*)(out + (((size_t)b * PADOUT + OFS + y) * PADOUT + OFS + xx) * 256 + co) = o;
            }
        }
    }
}

// NHWC [b][128][128][256] -> NCHW [b][256][128][128]
__global__ void __launch_bounds__(256)
transpose_kernel(const float* __restrict__ in, float* __restrict__ out) {
    __shared__ float s[32][33];
    const int tid = threadIdx.x;
    const int tx = tid & 7, ty = tid >> 3;
    const int x0 = blockIdx.x * 32;
    const int c0 = blockIdx.y * 32;
    const int b  = blockIdx.z >> 7;
    const int y  = blockIdx.z & 127;
    float4 v = *(const float4*)(in + (((size_t)b * 128 + y) * 128 + x0 + ty) * 256 + c0 + tx * 4);
    s[ty][tx * 4 + 0] = v.x; s[ty][tx * 4 + 1] = v.y;
    s[ty][tx * 4 + 2] = v.z; s[ty][tx * 4 + 3] = v.w;
    __syncthreads();
    float4 w;
    w.x = s[tx * 4 + 0][ty]; w.y = s[tx * 4 + 1][ty];
    w.z = s[tx * 4 + 2][ty]; w.w = s[tx * 4 + 3][ty];
    *(float4*)(out + (((size_t)b * 256 + c0 + ty) * 128 + y) * 128 + x0 + tx * 4) = w;
}

// rgb: warp per pixel, NHWC input, premodulated weights wm3[b][3][256]
__global__ void __launch_bounds__(256)
rgb_nhwc(const float* __restrict__ h2, const float* __restrict__ wm3,
         const float* __restrict__ b3, float* __restrict__ rgb) {
    const int gw = blockIdx.x * 8 + (threadIdx.x >> 5);
    const int lane = threadIdx.x & 31;
    const int b = gw >> 14, pix = gw & 16383;
    const float* hp = h2 + (size_t)gw * 256;
    float4 v0 = *(const float4*)(hp + lane * 4);
    float4 v1 = *(const float4*)(hp + 128 + lane * 4);
    float a[3];
#pragma unroll
    for (int r = 0; r < 3; r++) {
        const float* wp = wm3 + b * 768 + r * 256;
        float4 w0 = *(const float4*)(wp + lane * 4);
        float4 w1 = *(const float4*)(wp + 128 + lane * 4);
        a[r] = v0.x * w0.x + v0.y * w0.y + v0.z * w0.z + v0.w * w0.w
             + v1.x * w1.x + v1.y * w1.y + v1.z * w1.z + v1.w * w1.w;
#pragma unroll
        for (int o = 16; o; o >>= 1) a[r] += __shfl_xor_sync(~0u, a[r], o);
    }
    if (lane < 3) {
        float v = a[lane] + b3[lane];
        v = v > 0.f ? v : LRELU_S * v;
        rgb[((size_t)b * 3 + lane) * 16384 + pix] = v;
    }
}

extern "C" void kernel_launch(void* const* d_in, const int* in_sizes, int n_in,
                              void* d_out, int out_size) {
    const float* x   = (const float*)d_in[0];
    const float* w   = (const float*)d_in[1];
    const float* w1  = (const float*)d_in[2];
    const float* b1  = (const float*)d_in[3];
    const float* a1w = (const float*)d_in[4];
    const float* a1b = (const float*)d_in[5];
    const float* w2  = (const float*)d_in[6];
    const float* b2  = (const float*)d_in[7];
    const float* a2w = (const float*)d_in[8];
    const float* a2b = (const float*)d_in[9];
    const float* w3  = (const float*)d_in[10];
    const float* b3  = (const float*)d_in[11];
    const float* a3w = (const float*)d_in[12];
    const float* a3b = (const float*)d_in[13];

    float* out_h   = (float*)d_out;
    float* out_rgb = out_h + (size_t)B_ * COUT * HW * HW;

    float *xum, *h1m, *h2, *s1, *s2, *s3, *d1, *d2, *wsq1, *wsq2, *wpk1, *wpk2, *wm3;
    cudaGetSymbolAddress((void**)&xum,  g_xum);
    cudaGetSymbolAddress((void**)&h1m,  g_h1m);
    cudaGetSymbolAddress((void**)&h2,   g_h2);
    cudaGetSymbolAddress((void**)&s1,   g_s1);
    cudaGetSymbolAddress((void**)&s2,   g_s2);
    cudaGetSymbolAddress((void**)&s3,   g_s3);
    cudaGetSymbolAddress((void**)&d1,   g_d1);
    cudaGetSymbolAddress((void**)&d2,   g_d2);
    cudaGetSymbolAddress((void**)&wsq1, g_wsq1);
    cudaGetSymbolAddress((void**)&wsq2, g_wsq2);
    cudaGetSymbolAddress((void**)&wpk1, g_wpk1);
    cudaGetSymbolAddress((void**)&wpk2, g_wpk2);
    cudaGetSymbolAddress((void**)&wm3,  g_wm3);

    const int SMEM_DYN = (2 * 256 * 36 + 2 * 128 * 36) * 4;   // 110592 B
    cudaFuncSetAttribute(conv3x3_mma<512, 130, true>,
                         cudaFuncAttributeMaxDynamicSharedMemorySize, SMEM_DYN);
    cudaFuncSetAttribute(conv3x3_mma<256, 128, false>,
                         cudaFuncAttributeMaxDynamicSharedMemorySize, SMEM_DYN);

    // tiny prep kernels
    wsq_kernel<<<(256 * 512 + 255) / 256, 256>>>(w1, wsq1, 256 * 512);
    wsq_kernel<<<(256 * 256 + 255) / 256, 256>>>(w2, wsq2, 256 * 256);
    style_warp<<<(B_ * 512 * 32) / 256, 256>>>(w, a1w, a1b, s1, 512);
    style_warp<<<(B_ * 256 * 32) / 256, 256>>>(w, a2w, a2b, s2, 256);
    style_warp<<<(B_ * 256 * 32) / 256, 256>>>(w, a3w, a3b, s3, 256);
    demod_warp<<<(B_ * 256 * 32) / 256, 256>>>(s1, wsq1, d1, 512);
    demod_warp<<<(B_ * 256 * 32) / 256, 256>>>(s2, wsq2, d2, 256);
    prepack_kernel<<<(9 * 256 * 512 + 255) / 256, 256>>>(w1, wpk1, 512);
    prepack_kernel<<<(9 * 256 * 256 + 255) / 256, 256>>>(w2, wpk2, 256);
    rgbw_kernel<<<(B_ * 3 * 256 + 255) / 256, 256>>>(w3, s3, wm3);

    // upsample + modulate -> padded NHWC tf32
    upmod_kernel<<<dim3(4, 128, 64), 256>>>(x, s1, xum);

    // conv1: 512->256, epilogue *d1+b1, lrelu, *s2 -> h1m (padded NHWC tf32)
    conv3x3_mma<512, 130, true><<<dim3(64, 2, 4), 256, SMEM_DYN>>>(xum, wpk1, b1, d1, s2, h1m);
    // conv2: 256->256, epilogue *d2+b2, lrelu -> h2 (NHWC fp32)
    conv3x3_mma<256, 128, false><<<dim3(64, 2, 4), 256, SMEM_DYN>>>(h1m, wpk2, b2, d2,
                                                                    (const float*)nullptr, h2);
    // h: NHWC -> NCHW into d_out
    transpose_kernel<<<dim3(4, 8, 512), 256>>>(h2, out_h);
    // rgb from NHWC h
    rgb_nhwc<<<8192, 256>>>(h2, wm3, b3, out_rgb);
}